// round 16
// baseline (speedup 1.0000x reference)
#include <cuda_runtime.h>
#include <math.h>
#include <stdint.h>

#define NN 50000
#define EE 600000
#define HH 128
#define SCANB 98   // ceil(50000/512)

// ---------------- static device scratch (no allocs allowed) ----------------
__device__ float g_h[NN * HH];      // current node features
__device__ float g_hw[NN * HH];     // h @ W (GAT message tensor)
__device__ float g_as[NN * 8];      // alpha_src per node/head
__device__ float g_ad[NN * 8];      // alpha_dst per node/head
__device__ int   g_cnt[NN];
__device__ int   g_incl[NN];
__device__ int   g_rowoff[NN + 1];
__device__ int   g_cursor[NN];
__device__ int   g_bsum[SCANB];
__device__ int   g_csr[EE];

// ---------------- tf32 helpers ----------------------------------------------
__device__ __forceinline__ uint32_t f2tf32(float v) {
    uint32_t t;
    asm("cvt.rna.tf32.f32 %0, %1;" : "=r"(t) : "f"(v));
    return t;
}
__device__ __forceinline__ void mma_tf32(float& c0, float& c1, float& c2, float& c3,
                                         uint32_t a0, uint32_t a1, uint32_t a2, uint32_t a3,
                                         uint32_t b0, uint32_t b1) {
    asm volatile(
        "mma.sync.aligned.m16n8k8.row.col.f32.tf32.tf32.f32 "
        "{%0,%1,%2,%3}, {%4,%5,%6,%7}, {%8,%9}, {%0,%1,%2,%3};"
        : "+f"(c0), "+f"(c1), "+f"(c2), "+f"(c3)
        : "r"(a0), "r"(a1), "r"(a2), "r"(a3), "r"(b0), "r"(b1));
}

__device__ __forceinline__ int a_idx(int r, int c) {
    int mt = r >> 4, rr = r & 15, ks = c >> 3;
    int ln = ((rr & 7) << 2) | (c & 3);
    int rg = (rr >> 3) | (((c >> 2) & 1) << 1);
    return ((mt * 16 + ks) << 7) + (ln << 2) + rg;
}
__device__ __forceinline__ int b_idx(int n, int k) {
    int nt = n >> 3, nn = n & 7, ks = k >> 3;
    return ((nt * 16 + ks) << 6) + (((nn << 2) | (k & 3)) << 1) + ((k >> 2) & 1);
}

// ================= GAT projection GEMM (R11-proven) =========================
template <bool FUSEIN>
__global__ void __launch_bounds__(256, 2) gat_gemm(
    const float* __restrict__ A, const float* __restrict__ xin,
    const float* __restrict__ Win, const float* __restrict__ bin,
    const float* __restrict__ W,
    const float* __restrict__ asv, const float* __restrict__ adv) {
    extern __shared__ float sm[];
    float* As = sm;
    float* Bs = sm + 16384;
    int tid = threadIdx.x;
    int row0 = blockIdx.x * 128;

    int w = tid >> 5, lane = tid & 31;
    int wm = w >> 1, wn = w & 1;
    int grp = lane >> 2, qd = lane & 3;

#pragma unroll
    for (int j = 0; j < 8; j++) {
        int i = tid * 4 + j * 1024;
        int k = i >> 6, n = i & 63;
        float4 wv = *reinterpret_cast<const float4*>(&W[(size_t)k * 128 + n]);
#pragma unroll
        for (int e = 0; e < 4; e++)
            Bs[b_idx(n + e, k)] = __uint_as_float(f2tf32((&wv.x)[e]));
    }
    for (int g = tid; g < 2048; g += 256) {
        int r = g >> 4, c = (g & 15) * 4;
        int gr = row0 + r; if (gr >= NN) gr = NN - 1;
        float4 v;
        if (FUSEIN) {
            float x0 = xin[gr * 2], x1 = xin[gr * 2 + 1];
            float4 w0 = *reinterpret_cast<const float4*>(&Win[c]);
            float4 w1 = *reinterpret_cast<const float4*>(&Win[128 + c]);
            float4 bb = *reinterpret_cast<const float4*>(&bin[c]);
            v.x = fmaf(x0, w0.x, fmaf(x1, w1.x, bb.x));
            v.y = fmaf(x0, w0.y, fmaf(x1, w1.y, bb.y));
            v.z = fmaf(x0, w0.z, fmaf(x1, w1.z, bb.z));
            v.w = fmaf(x0, w0.w, fmaf(x1, w1.w, bb.w));
            *reinterpret_cast<float4*>(&g_h[(size_t)gr * 128 + c]) = v;
        } else {
            v = *reinterpret_cast<const float4*>(&A[(size_t)gr * 128 + c]);
        }
#pragma unroll
        for (int e = 0; e < 4; e++)
            As[a_idx(r, c + e)] = __uint_as_float(f2tf32((&v.x)[e]));
    }
    float4 pf[8];
#pragma unroll
    for (int j = 0; j < 8; j++) {
        int g = j * 256 + tid;
        int r = g >> 4, c = 64 + (g & 15) * 4;
        int gr = row0 + r; if (gr >= NN) gr = NN - 1;
        if (FUSEIN) {
            float x0 = xin[gr * 2], x1 = xin[gr * 2 + 1];
            float4 w0 = *reinterpret_cast<const float4*>(&Win[c]);
            float4 w1 = *reinterpret_cast<const float4*>(&Win[128 + c]);
            float4 bb = *reinterpret_cast<const float4*>(&bin[c]);
            float4 v;
            v.x = fmaf(x0, w0.x, fmaf(x1, w1.x, bb.x));
            v.y = fmaf(x0, w0.y, fmaf(x1, w1.y, bb.y));
            v.z = fmaf(x0, w0.z, fmaf(x1, w1.z, bb.z));
            v.w = fmaf(x0, w0.w, fmaf(x1, w1.w, bb.w));
            *reinterpret_cast<float4*>(&g_h[(size_t)gr * 128 + c]) = v;
            pf[j] = v;
        } else {
            pf[j] = *reinterpret_cast<const float4*>(&A[(size_t)gr * 128 + c]);
        }
    }
    __syncthreads();

    float acc[2][4][4];
    auto compute = [&](int ks0, int ks1) {
        for (int ks = ks0; ks < ks1; ks++) {
            uint32_t af[2][4];
#pragma unroll
            for (int mi = 0; mi < 2; mi++) {
                float4 v = *reinterpret_cast<const float4*>(
                    &As[(((wm * 2 + mi) * 16 + ks) << 7) + (lane << 2)]);
                af[mi][0] = __float_as_uint(v.x); af[mi][1] = __float_as_uint(v.y);
                af[mi][2] = __float_as_uint(v.z); af[mi][3] = __float_as_uint(v.w);
            }
            uint32_t bf[4][2];
#pragma unroll
            for (int ni = 0; ni < 4; ni++) {
                float2 v = *reinterpret_cast<const float2*>(
                    &Bs[(((wn * 4 + ni) * 16 + ks) << 6) + (lane << 1)]);
                bf[ni][0] = __float_as_uint(v.x); bf[ni][1] = __float_as_uint(v.y);
            }
#pragma unroll
            for (int mi = 0; mi < 2; mi++)
#pragma unroll
                for (int ni = 0; ni < 4; ni++)
                    mma_tf32(acc[mi][ni][0], acc[mi][ni][1], acc[mi][ni][2], acc[mi][ni][3],
                             af[mi][0], af[mi][1], af[mi][2], af[mi][3],
                             bf[ni][0], bf[ni][1]);
        }
    };

    auto epilogue = [&](int colbase) {
        float asr[2][2][2], adr[2][2][2];
#pragma unroll
        for (int mi = 0; mi < 2; mi++)
#pragma unroll
            for (int rh = 0; rh < 2; rh++)
#pragma unroll
                for (int hp = 0; hp < 2; hp++) { asr[mi][rh][hp] = 0.f; adr[mi][rh][hp] = 0.f; }
#pragma unroll
        for (int mi = 0; mi < 2; mi++) {
#pragma unroll
            for (int ni = 0; ni < 4; ni++) {
                int cb = colbase + wn * 32 + ni * 8 + (qd << 1);
                int r = row0 + wm * 32 + mi * 16 + grp;
                float v0 = acc[mi][ni][0], v1 = acc[mi][ni][1];
                float v2 = acc[mi][ni][2], v3 = acc[mi][ni][3];
                int hp = ni >> 1;
                float a0 = asv[cb], a1 = asv[cb + 1];
                float d0 = adv[cb], d1 = adv[cb + 1];
                asr[mi][0][hp] += v0 * a0 + v1 * a1;
                asr[mi][1][hp] += v2 * a0 + v3 * a1;
                adr[mi][0][hp] += v0 * d0 + v1 * d1;
                adr[mi][1][hp] += v2 * d0 + v3 * d1;
                if (r < NN)
                    *reinterpret_cast<float2*>(&g_hw[(size_t)r * 128 + cb]) = make_float2(v0, v1);
                if (r + 8 < NN)
                    *reinterpret_cast<float2*>(&g_hw[(size_t)(r + 8) * 128 + cb]) = make_float2(v2, v3);
            }
        }
#pragma unroll
        for (int mi = 0; mi < 2; mi++)
#pragma unroll
            for (int rh = 0; rh < 2; rh++)
#pragma unroll
                for (int hp = 0; hp < 2; hp++) {
                    float a = asr[mi][rh][hp], d = adr[mi][rh][hp];
                    a += __shfl_xor_sync(0xffffffffu, a, 1);
                    a += __shfl_xor_sync(0xffffffffu, a, 2);
                    d += __shfl_xor_sync(0xffffffffu, d, 1);
                    d += __shfl_xor_sync(0xffffffffu, d, 2);
                    asr[mi][rh][hp] = a; adr[mi][rh][hp] = d;
                }
        if (qd == 0) {
            int h0 = (colbase + wn * 32) >> 4;
#pragma unroll
            for (int mi = 0; mi < 2; mi++)
#pragma unroll
                for (int rh = 0; rh < 2; rh++) {
                    int r = row0 + wm * 32 + mi * 16 + grp + rh * 8;
                    if (r < NN) {
#pragma unroll
                        for (int hp = 0; hp < 2; hp++) {
                            g_as[r * 8 + h0 + hp] = asr[mi][rh][hp];
                            g_ad[r * 8 + h0 + hp] = adr[mi][rh][hp];
                        }
                    }
                }
        }
    };

#pragma unroll
    for (int mi = 0; mi < 2; mi++)
#pragma unroll
        for (int ni = 0; ni < 4; ni++)
#pragma unroll
            for (int j = 0; j < 4; j++) acc[mi][ni][j] = 0.f;
    compute(0, 8);
    __syncthreads();
#pragma unroll
    for (int j = 0; j < 8; j++) {
        int g = j * 256 + tid;
        int r = g >> 4, c = 64 + (g & 15) * 4;
#pragma unroll
        for (int e = 0; e < 4; e++)
            As[a_idx(r, c + e)] = __uint_as_float(f2tf32((&pf[j].x)[e]));
    }
    __syncthreads();
    compute(8, 16);
    float4 pfB[8];
#pragma unroll
    for (int j = 0; j < 8; j++) {
        int i = tid * 4 + j * 1024;
        int k = i >> 6, n = i & 63;
        pfB[j] = *reinterpret_cast<const float4*>(&W[(size_t)k * 128 + 64 + n]);
    }
    epilogue(0);

    __syncthreads();
#pragma unroll
    for (int j = 0; j < 8; j++) {
        int i = tid * 4 + j * 1024;
        int k = i >> 6, n = i & 63;
#pragma unroll
        for (int e = 0; e < 4; e++)
            Bs[b_idx(n + e, k)] = __uint_as_float(f2tf32((&pfB[j].x)[e]));
    }
    __syncthreads();
#pragma unroll
    for (int mi = 0; mi < 2; mi++)
#pragma unroll
        for (int ni = 0; ni < 4; ni++)
#pragma unroll
            for (int j = 0; j < 4; j++) acc[mi][ni][j] = 0.f;
    compute(0, 16);
    epilogue(64);
}

// ================= fused MLP head (R11-proven) ==============================
__global__ void __launch_bounds__(256, 2) mlp_kernel(
    const float* __restrict__ W1, const float* __restrict__ b1,
    const float* __restrict__ W2, const float* __restrict__ b2,
    const float* __restrict__ W3, const float* __restrict__ b3,
    float* __restrict__ out) {
    extern __shared__ float sm[];
    float* As = sm;
    float* Bs = sm + 16384;
    __shared__ float hsum[128];
    int tid = threadIdx.x;
    int row0 = blockIdx.x * 128;
    int w = tid >> 5, lane = tid & 31;
    int wm = w >> 1, wn = w & 1;
    int grp = lane >> 2, qd = lane & 3;

#pragma unroll
    for (int j = 0; j < 8; j++) {
        int i = tid * 4 + j * 1024;
        int k = i >> 6, n = i & 63;
        float4 wv = *reinterpret_cast<const float4*>(&W1[(size_t)k * 128 + n]);
#pragma unroll
        for (int e = 0; e < 4; e++)
            Bs[b_idx(n + e, k)] = __uint_as_float(f2tf32((&wv.x)[e]));
    }
    for (int g = tid; g < 2048; g += 256) {
        int r = g >> 4, c = (g & 15) * 4;
        int gr = row0 + r; if (gr >= NN) gr = NN - 1;
        float4 v = *reinterpret_cast<const float4*>(&g_h[(size_t)gr * 128 + c]);
#pragma unroll
        for (int e = 0; e < 4; e++)
            As[a_idx(r, c + e)] = __uint_as_float(f2tf32((&v.x)[e]));
    }
    float4 pf[8];
#pragma unroll
    for (int j = 0; j < 8; j++) {
        int g = j * 256 + tid;
        int r = g >> 4, c = 64 + (g & 15) * 4;
        int gr = row0 + r; if (gr >= NN) gr = NN - 1;
        pf[j] = *reinterpret_cast<const float4*>(&g_h[(size_t)gr * 128 + c]);
    }
    __syncthreads();

    float acc0[2][4][4], acc1[2][4][4];
    auto compute = [&](float (&acc)[2][4][4], int ks0, int ks1) {
        for (int ks = ks0; ks < ks1; ks++) {
            uint32_t af[2][4];
#pragma unroll
            for (int mi = 0; mi < 2; mi++) {
                float4 v = *reinterpret_cast<const float4*>(
                    &As[(((wm * 2 + mi) * 16 + ks) << 7) + (lane << 2)]);
                af[mi][0] = __float_as_uint(v.x); af[mi][1] = __float_as_uint(v.y);
                af[mi][2] = __float_as_uint(v.z); af[mi][3] = __float_as_uint(v.w);
            }
            uint32_t bf[4][2];
#pragma unroll
            for (int ni = 0; ni < 4; ni++) {
                float2 v = *reinterpret_cast<const float2*>(
                    &Bs[(((wn * 4 + ni) * 16 + ks) << 6) + (lane << 1)]);
                bf[ni][0] = __float_as_uint(v.x); bf[ni][1] = __float_as_uint(v.y);
            }
#pragma unroll
            for (int mi = 0; mi < 2; mi++)
#pragma unroll
                for (int ni = 0; ni < 4; ni++)
                    mma_tf32(acc[mi][ni][0], acc[mi][ni][1], acc[mi][ni][2], acc[mi][ni][3],
                             af[mi][0], af[mi][1], af[mi][2], af[mi][3],
                             bf[ni][0], bf[ni][1]);
        }
    };

#pragma unroll
    for (int mi = 0; mi < 2; mi++)
#pragma unroll
        for (int ni = 0; ni < 4; ni++)
#pragma unroll
            for (int j = 0; j < 4; j++) acc0[mi][ni][j] = 0.f;
    compute(acc0, 0, 8);
    __syncthreads();
#pragma unroll
    for (int j = 0; j < 8; j++) {
        int g = j * 256 + tid;
        int r = g >> 4, c = 64 + (g & 15) * 4;
#pragma unroll
        for (int e = 0; e < 4; e++)
            As[a_idx(r, c + e)] = __uint_as_float(f2tf32((&pf[j].x)[e]));
    }
    __syncthreads();
    compute(acc0, 8, 16);
    float4 pfB[8];
#pragma unroll
    for (int j = 0; j < 8; j++) {
        int i = tid * 4 + j * 1024;
        int k = i >> 6, n = i & 63;
        pfB[j] = *reinterpret_cast<const float4*>(&W1[(size_t)k * 128 + 64 + n]);
    }
    __syncthreads();
#pragma unroll
    for (int j = 0; j < 8; j++) {
        int i = tid * 4 + j * 1024;
        int k = i >> 6, n = i & 63;
#pragma unroll
        for (int e = 0; e < 4; e++)
            Bs[b_idx(n + e, k)] = __uint_as_float(f2tf32((&pfB[j].x)[e]));
    }
    __syncthreads();
#pragma unroll
    for (int mi = 0; mi < 2; mi++)
#pragma unroll
        for (int ni = 0; ni < 4; ni++)
#pragma unroll
            for (int j = 0; j < 4; j++) acc1[mi][ni][j] = 0.f;
    compute(acc1, 0, 16);
    __syncthreads();

#pragma unroll
    for (int mi = 0; mi < 2; mi++) {
#pragma unroll
        for (int ni = 0; ni < 4; ni++) {
            int c0 = wn * 32 + ni * 8 + (qd << 1);
            int r0 = wm * 32 + mi * 16 + grp;
            float bb0 = b1[c0], bb1 = b1[c0 + 1];
            As[a_idx(r0, c0)]     = __uint_as_float(f2tf32(fmaxf(acc0[mi][ni][0] + bb0, 0.f)));
            As[a_idx(r0, c0 + 1)] = __uint_as_float(f2tf32(fmaxf(acc0[mi][ni][1] + bb1, 0.f)));
            As[a_idx(r0 + 8, c0)]     = __uint_as_float(f2tf32(fmaxf(acc0[mi][ni][2] + bb0, 0.f)));
            As[a_idx(r0 + 8, c0 + 1)] = __uint_as_float(f2tf32(fmaxf(acc0[mi][ni][3] + bb1, 0.f)));
            int c1 = c0 + 64;
            float cb0 = b1[c1], cb1 = b1[c1 + 1];
            As[a_idx(r0, c1)]     = __uint_as_float(f2tf32(fmaxf(acc1[mi][ni][0] + cb0, 0.f)));
            As[a_idx(r0, c1 + 1)] = __uint_as_float(f2tf32(fmaxf(acc1[mi][ni][1] + cb1, 0.f)));
            As[a_idx(r0 + 8, c1)]     = __uint_as_float(f2tf32(fmaxf(acc1[mi][ni][2] + cb0, 0.f)));
            As[a_idx(r0 + 8, c1 + 1)] = __uint_as_float(f2tf32(fmaxf(acc1[mi][ni][3] + cb1, 0.f)));
        }
    }
#pragma unroll
    for (int j = 0; j < 8; j++) {
        int i = tid * 4 + j * 1024;
        int k = i >> 6, n = i & 63;
        float4 wv = *reinterpret_cast<const float4*>(&W2[(size_t)k * 64 + n]);
#pragma unroll
        for (int e = 0; e < 4; e++)
            Bs[b_idx(n + e, k)] = __uint_as_float(f2tf32((&wv.x)[e]));
    }
    __syncthreads();

#pragma unroll
    for (int mi = 0; mi < 2; mi++)
#pragma unroll
        for (int ni = 0; ni < 4; ni++)
#pragma unroll
            for (int j = 0; j < 4; j++) acc0[mi][ni][j] = 0.f;
    compute(acc0, 0, 16);

    float pr[2][2] = {{0.f, 0.f}, {0.f, 0.f}};
#pragma unroll
    for (int mi = 0; mi < 2; mi++) {
#pragma unroll
        for (int ni = 0; ni < 4; ni++) {
            int cb = wn * 32 + ni * 8 + (qd << 1);
            float bb0 = b2[cb], bb1 = b2[cb + 1];
            float w0 = W3[cb], w1 = W3[cb + 1];
            float v0 = fmaxf(acc0[mi][ni][0] + bb0, 0.f);
            float v1 = fmaxf(acc0[mi][ni][1] + bb1, 0.f);
            float v2 = fmaxf(acc0[mi][ni][2] + bb0, 0.f);
            float v3 = fmaxf(acc0[mi][ni][3] + bb1, 0.f);
            pr[mi][0] += v0 * w0 + v1 * w1;
            pr[mi][1] += v2 * w0 + v3 * w1;
        }
    }
#pragma unroll
    for (int mi = 0; mi < 2; mi++)
#pragma unroll
        for (int rh = 0; rh < 2; rh++) {
            float p = pr[mi][rh];
            p += __shfl_xor_sync(0xffffffffu, p, 1);
            p += __shfl_xor_sync(0xffffffffu, p, 2);
            pr[mi][rh] = p;
        }
    if (wn == 0 && qd == 0) {
#pragma unroll
        for (int mi = 0; mi < 2; mi++)
#pragma unroll
            for (int rh = 0; rh < 2; rh++)
                hsum[wm * 32 + mi * 16 + grp + rh * 8] = pr[mi][rh];
    }
    __syncthreads();
    if (wn == 1 && qd == 0) {
        float bb = b3[0];
#pragma unroll
        for (int mi = 0; mi < 2; mi++)
#pragma unroll
            for (int rh = 0; rh < 2; rh++) {
                int local = wm * 32 + mi * 16 + grp + rh * 8;
                int r = row0 + local;
                if (r < NN) out[r] = hsum[local] + pr[mi][rh] + bb;
            }
    }
}

// ---------------- CSR build (R14-proven: scalar count/scatter) ---------------
__global__ void count_kernel(const int* __restrict__ dst) {
    int e = blockIdx.x * blockDim.x + threadIdx.x;
    if (e < EE) atomicAdd(&g_cnt[dst[e]], 1);
}
__global__ void scan1() {
    __shared__ int sm[512];
    int i = blockIdx.x * 512 + threadIdx.x;
    int v = (i < NN) ? g_cnt[i] : 0;
    sm[threadIdx.x] = v;
    __syncthreads();
    for (int off = 1; off < 512; off <<= 1) {
        int t = (threadIdx.x >= off) ? sm[threadIdx.x - off] : 0;
        __syncthreads();
        sm[threadIdx.x] += t;
        __syncthreads();
    }
    if (i < NN) g_incl[i] = sm[threadIdx.x];
    if (threadIdx.x == 511) g_bsum[blockIdx.x] = sm[511];
}
__global__ void __launch_bounds__(256) scan23() {
    __shared__ int tmp[128];
    __shared__ int bex[SCANB];
    int tid = threadIdx.x;
    if (tid < 128) tmp[tid] = (tid < SCANB) ? g_bsum[tid] : 0;
    __syncthreads();
    int myv = (tid < 128) ? tmp[tid] : 0;
    for (int off = 1; off < 128; off <<= 1) {
        int t = (tid < 128 && tid >= off) ? tmp[tid - off] : 0;
        __syncthreads();
        if (tid < 128) tmp[tid] += t;
        __syncthreads();
    }
    if (tid < SCANB) bex[tid] = tmp[tid] - myv;
    __syncthreads();
    int i = blockIdx.x * blockDim.x + tid;
    if (i < NN) {
        int off = g_incl[i] - g_cnt[i] + bex[i >> 9];
        g_rowoff[i] = off;
        g_cursor[i] = off;
    }
    if (i == 0) g_rowoff[NN] = EE;
}
__global__ void scatter(const int* __restrict__ src, const int* __restrict__ dst) {
    int e = blockIdx.x * blockDim.x + threadIdx.x;
    if (e < EE) {
        int d = dst[e];
        int pos = atomicAdd(&g_cursor[d], 1);
        g_csr[pos] = src[e];
    }
}

__device__ __forceinline__ float lrelu(float t) { return t > 0.f ? t : 0.2f * t; }

// ---------------- aggregate: 2 warps per node, 4-way unroll ------------------
// block = 256 threads = 8 warps = 4 nodes x 2 warps. Warps of a pair take
// alternating 4-edge chunks; partials combined through SMEM; warp 0 of each
// pair runs the softmax-normalize + bias + relu + residual + LN epilogue.
__global__ void __launch_bounds__(256) aggregate_kernel(
    const float* __restrict__ gb, const float* __restrict__ lng,
    const float* __restrict__ lnb) {
    __shared__ float part[4][32][5];
    int warp = threadIdx.x >> 5;
    int nib = warp >> 1;          // node in block 0..3
    int wp = warp & 1;            // which warp of the pair
    int n = blockIdx.x * 4 + nib; // NN = 50000 = 12500 * 4, always valid
    int lane = threadIdx.x & 31;
    int mh = lane >> 2;
    int c0 = lane * 4;
    int beg = g_rowoff[n], end = g_rowoff[n + 1];

    float admh = g_ad[n * 8 + mh];
    float den = 0.f, a0 = 0.f, a1 = 0.f, a2 = 0.f, a3 = 0.f;
    if (wp == 0) {  // self loop
        float asmh = g_as[n * 8 + mh];
        float wself = __expf(lrelu(asmh + admh));
        den = wself;
        float4 v = *reinterpret_cast<const float4*>(&g_hw[(size_t)n * 128 + c0]);
        a0 = v.x * wself; a1 = v.y * wself; a2 = v.z * wself; a3 = v.w * wself;
    }
    for (int base = beg + wp * 4; base < end; base += 8) {
        int m = end - base; if (m > 4) m = 4;
        if (m == 4) {
            int s0 = g_csr[base], s1 = g_csr[base + 1], s2 = g_csr[base + 2], s3 = g_csr[base + 3];
            float l0 = g_as[s0 * 8 + mh], l1 = g_as[s1 * 8 + mh];
            float l2 = g_as[s2 * 8 + mh], l3 = g_as[s3 * 8 + mh];
            float4 v0 = *reinterpret_cast<const float4*>(&g_hw[(size_t)s0 * 128 + c0]);
            float4 v1 = *reinterpret_cast<const float4*>(&g_hw[(size_t)s1 * 128 + c0]);
            float4 v2 = *reinterpret_cast<const float4*>(&g_hw[(size_t)s2 * 128 + c0]);
            float4 v3 = *reinterpret_cast<const float4*>(&g_hw[(size_t)s3 * 128 + c0]);
            float w0 = __expf(lrelu(l0 + admh));
            float w1 = __expf(lrelu(l1 + admh));
            float w2 = __expf(lrelu(l2 + admh));
            float w3 = __expf(lrelu(l3 + admh));
            den += (w0 + w1) + (w2 + w3);
            a0 = fmaf(v0.x, w0, fmaf(v1.x, w1, fmaf(v2.x, w2, fmaf(v3.x, w3, a0))));
            a1 = fmaf(v0.y, w0, fmaf(v1.y, w1, fmaf(v2.y, w2, fmaf(v3.y, w3, a1))));
            a2 = fmaf(v0.z, w0, fmaf(v1.z, w1, fmaf(v2.z, w2, fmaf(v3.z, w3, a2))));
            a3 = fmaf(v0.w, w0, fmaf(v1.w, w1, fmaf(v2.w, w2, fmaf(v3.w, w3, a3))));
        } else {
            for (int j = 0; j < m; j++) {
                int s = g_csr[base + j];
                float wgt = __expf(lrelu(g_as[s * 8 + mh] + admh));
                float4 v = *reinterpret_cast<const float4*>(&g_hw[(size_t)s * 128 + c0]);
                den += wgt;
                a0 = fmaf(v.x, wgt, a0);
                a1 = fmaf(v.y, wgt, a1);
                a2 = fmaf(v.z, wgt, a2);
                a3 = fmaf(v.w, wgt, a3);
            }
        }
    }
    // combine pair partials through SMEM
    if (wp == 1) {
        part[nib][lane][0] = a0;
        part[nib][lane][1] = a1;
        part[nib][lane][2] = a2;
        part[nib][lane][3] = a3;
        part[nib][lane][4] = den;
    }
    __syncthreads();
    if (wp == 1) return;
    a0 += part[nib][lane][0];
    a1 += part[nib][lane][1];
    a2 += part[nib][lane][2];
    a3 += part[nib][lane][3];
    den += part[nib][lane][4];

    float iv = 1.0f / den;
    float4 b4 = *reinterpret_cast<const float4*>(&gb[c0]);
    float v0 = fmaxf(fmaf(a0, iv, b4.x), 0.f), v1 = fmaxf(fmaf(a1, iv, b4.y), 0.f);
    float v2 = fmaxf(fmaf(a2, iv, b4.z), 0.f), v3 = fmaxf(fmaf(a3, iv, b4.w), 0.f);
    float4 r4 = *reinterpret_cast<const float4*>(&g_h[(size_t)n * 128 + c0]);
    v0 += r4.x; v1 += r4.y; v2 += r4.z; v3 += r4.w;
    float s1 = v0 + v1 + v2 + v3;
    float s2 = v0 * v0 + v1 * v1 + v2 * v2 + v3 * v3;
#pragma unroll
    for (int off = 16; off; off >>= 1) {
        s1 += __shfl_xor_sync(0xffffffffu, s1, off);
        s2 += __shfl_xor_sync(0xffffffffu, s2, off);
    }
    float mu = s1 * (1.f / 128.f);
    float var = s2 * (1.f / 128.f) - mu * mu;
    float rstd = rsqrtf(fmaxf(var, 0.f) + 1e-5f);
    float4 g4 = *reinterpret_cast<const float4*>(&lng[c0]);
    float4 bb4 = *reinterpret_cast<const float4*>(&lnb[c0]);
    float4 o;
    o.x = (v0 - mu) * rstd * g4.x + bb4.x;
    o.y = (v1 - mu) * rstd * g4.y + bb4.y;
    o.z = (v2 - mu) * rstd * g4.z + bb4.z;
    o.w = (v3 - mu) * rstd * g4.w + bb4.w;
    *reinterpret_cast<float4*>(&g_h[(size_t)n * 128 + c0]) = o;
}

// ---------------- launch ----------------------------------------------------
extern "C" void kernel_launch(void* const* d_in, const int* in_sizes, int n_in,
                              void* d_out, int out_size) {
    const float* x = (const float*)d_in[0];
    const int* ei = (const int*)d_in[1];
    const int* src = ei;
    const int* dst = ei + EE;
    const float* W_in = (const float*)d_in[3];
    const float* b_in = (const float*)d_in[4];
    float* out = (float*)d_out;

    float* p_h = nullptr;
    int* p_cnt = nullptr;
    cudaGetSymbolAddress((void**)&p_h, g_h);
    cudaGetSymbolAddress((void**)&p_cnt, g_cnt);

    const int SMEM_GEMM = (16384 + 8192) * 4;  // 96 KB
    cudaFuncSetAttribute(gat_gemm<true>,  cudaFuncAttributeMaxDynamicSharedMemorySize, SMEM_GEMM);
    cudaFuncSetAttribute(gat_gemm<false>, cudaFuncAttributeMaxDynamicSharedMemorySize, SMEM_GEMM);
    cudaFuncSetAttribute(mlp_kernel,      cudaFuncAttributeMaxDynamicSharedMemorySize, SMEM_GEMM);
    const int NCTA = (NN + 127) / 128;  // 391

    // fork the CSR build onto a second stream, overlapping the layer-0 GEMM
    cudaStream_t s2;
    cudaEvent_t ev1, ev2;
    cudaStreamCreateWithFlags(&s2, cudaStreamNonBlocking);
    cudaEventCreateWithFlags(&ev1, cudaEventDisableTiming);
    cudaEventCreateWithFlags(&ev2, cudaEventDisableTiming);

    cudaEventRecord(ev1, 0);
    cudaStreamWaitEvent(s2, ev1, 0);
    cudaMemsetAsync(p_cnt, 0, NN * sizeof(int), s2);
    count_kernel<<<(EE + 255) / 256, 256, 0, s2>>>(dst);
    scan1<<<(NN + 511) / 512, 512, 0, s2>>>();
    scan23<<<(NN + 255) / 256, 256, 0, s2>>>();
    scatter<<<(EE + 255) / 256, 256, 0, s2>>>(src, dst);
    cudaEventRecord(ev2, s2);

    // layer 0 GEMM on main stream (independent of CSR)
    gat_gemm<true><<<NCTA, 256, SMEM_GEMM>>>(
        nullptr, x, W_in, b_in, (const float*)d_in[5],
        (const float*)d_in[6], (const float*)d_in[7]);
    cudaStreamWaitEvent(0, ev2, 0);   // join: aggregate needs the CSR

    for (int l = 0; l < 3; l++) {
        const float* gb = (const float*)d_in[8 + 6 * l];
        const float* lg = (const float*)d_in[9 + 6 * l];
        const float* lb = (const float*)d_in[10 + 6 * l];
        if (l > 0) {
            const float* W  = (const float*)d_in[5 + 6 * l];
            const float* as = (const float*)d_in[6 + 6 * l];
            const float* ad = (const float*)d_in[7 + 6 * l];
            gat_gemm<false><<<NCTA, 256, SMEM_GEMM>>>(p_h, nullptr, nullptr, nullptr, W, as, ad);
        }
        aggregate_kernel<<<NN / 4, 256>>>(gb, lg, lb);
    }
    mlp_kernel<<<NCTA, 256, SMEM_GEMM>>>((const float*)d_in[23], (const float*)d_in[24],
                                         (const float*)d_in[25], (const float*)d_in[26],
                                         (const float*)d_in[27], (const float*)d_in[28], out);
}

// round 17
// speedup vs baseline: 1.1547x; 1.1547x over previous
#include <cuda_runtime.h>
#include <math.h>
#include <stdint.h>

#define NN 50000
#define EE 600000
#define HH 128
#define SCANB 98   // ceil(50000/512)

// ---------------- static device scratch (no allocs allowed) ----------------
__device__ float g_h[NN * HH];      // current node features
__device__ float g_hw[NN * HH];     // h @ W (GAT message tensor)
__device__ float g_as[NN * 8];      // alpha_src per node/head
__device__ float g_ad[NN * 8];      // alpha_dst per node/head
__device__ int   g_cnt[NN];         // zero-initialized; re-zeroed by scan23 each run
__device__ int   g_incl[NN];
__device__ int   g_rowoff[NN + 1];
__device__ int   g_cursor[NN];
__device__ int   g_bsum[SCANB];
__device__ int   g_csr[EE];

// ---------------- tf32 helpers ----------------------------------------------
__device__ __forceinline__ uint32_t f2tf32(float v) {
    uint32_t t;
    asm("cvt.rna.tf32.f32 %0, %1;" : "=r"(t) : "f"(v));
    return t;
}
__device__ __forceinline__ void mma_tf32(float& c0, float& c1, float& c2, float& c3,
                                         uint32_t a0, uint32_t a1, uint32_t a2, uint32_t a3,
                                         uint32_t b0, uint32_t b1) {
    asm volatile(
        "mma.sync.aligned.m16n8k8.row.col.f32.tf32.tf32.f32 "
        "{%0,%1,%2,%3}, {%4,%5,%6,%7}, {%8,%9}, {%0,%1,%2,%3};"
        : "+f"(c0), "+f"(c1), "+f"(c2), "+f"(c3)
        : "r"(a0), "r"(a1), "r"(a2), "r"(a3), "r"(b0), "r"(b1));
}

__device__ __forceinline__ int a_idx(int r, int c) {
    int mt = r >> 4, rr = r & 15, ks = c >> 3;
    int ln = ((rr & 7) << 2) | (c & 3);
    int rg = (rr >> 3) | (((c >> 2) & 1) << 1);
    return ((mt * 16 + ks) << 7) + (ln << 2) + rg;
}
__device__ __forceinline__ int b_idx(int n, int k) {
    int nt = n >> 3, nn = n & 7, ks = k >> 3;
    return ((nt * 16 + ks) << 6) + (((nn << 2) | (k & 3)) << 1) + ((k >> 2) & 1);
}

// ================= GAT projection GEMM (R11-proven) =========================
template <bool FUSEIN>
__global__ void __launch_bounds__(256, 2) gat_gemm(
    const float* __restrict__ A, const float* __restrict__ xin,
    const float* __restrict__ Win, const float* __restrict__ bin,
    const float* __restrict__ W,
    const float* __restrict__ asv, const float* __restrict__ adv) {
    extern __shared__ float sm[];
    float* As = sm;
    float* Bs = sm + 16384;
    int tid = threadIdx.x;
    int row0 = blockIdx.x * 128;

    int w = tid >> 5, lane = tid & 31;
    int wm = w >> 1, wn = w & 1;
    int grp = lane >> 2, qd = lane & 3;

#pragma unroll
    for (int j = 0; j < 8; j++) {
        int i = tid * 4 + j * 1024;
        int k = i >> 6, n = i & 63;
        float4 wv = *reinterpret_cast<const float4*>(&W[(size_t)k * 128 + n]);
#pragma unroll
        for (int e = 0; e < 4; e++)
            Bs[b_idx(n + e, k)] = __uint_as_float(f2tf32((&wv.x)[e]));
    }
    for (int g = tid; g < 2048; g += 256) {
        int r = g >> 4, c = (g & 15) * 4;
        int gr = row0 + r; if (gr >= NN) gr = NN - 1;
        float4 v;
        if (FUSEIN) {
            float x0 = xin[gr * 2], x1 = xin[gr * 2 + 1];
            float4 w0 = *reinterpret_cast<const float4*>(&Win[c]);
            float4 w1 = *reinterpret_cast<const float4*>(&Win[128 + c]);
            float4 bb = *reinterpret_cast<const float4*>(&bin[c]);
            v.x = fmaf(x0, w0.x, fmaf(x1, w1.x, bb.x));
            v.y = fmaf(x0, w0.y, fmaf(x1, w1.y, bb.y));
            v.z = fmaf(x0, w0.z, fmaf(x1, w1.z, bb.z));
            v.w = fmaf(x0, w0.w, fmaf(x1, w1.w, bb.w));
            *reinterpret_cast<float4*>(&g_h[(size_t)gr * 128 + c]) = v;
        } else {
            v = *reinterpret_cast<const float4*>(&A[(size_t)gr * 128 + c]);
        }
#pragma unroll
        for (int e = 0; e < 4; e++)
            As[a_idx(r, c + e)] = __uint_as_float(f2tf32((&v.x)[e]));
    }
    float4 pf[8];
#pragma unroll
    for (int j = 0; j < 8; j++) {
        int g = j * 256 + tid;
        int r = g >> 4, c = 64 + (g & 15) * 4;
        int gr = row0 + r; if (gr >= NN) gr = NN - 1;
        if (FUSEIN) {
            float x0 = xin[gr * 2], x1 = xin[gr * 2 + 1];
            float4 w0 = *reinterpret_cast<const float4*>(&Win[c]);
            float4 w1 = *reinterpret_cast<const float4*>(&Win[128 + c]);
            float4 bb = *reinterpret_cast<const float4*>(&bin[c]);
            float4 v;
            v.x = fmaf(x0, w0.x, fmaf(x1, w1.x, bb.x));
            v.y = fmaf(x0, w0.y, fmaf(x1, w1.y, bb.y));
            v.z = fmaf(x0, w0.z, fmaf(x1, w1.z, bb.z));
            v.w = fmaf(x0, w0.w, fmaf(x1, w1.w, bb.w));
            *reinterpret_cast<float4*>(&g_h[(size_t)gr * 128 + c]) = v;
            pf[j] = v;
        } else {
            pf[j] = *reinterpret_cast<const float4*>(&A[(size_t)gr * 128 + c]);
        }
    }
    __syncthreads();

    float acc[2][4][4];
    auto compute = [&](int ks0, int ks1) {
        for (int ks = ks0; ks < ks1; ks++) {
            uint32_t af[2][4];
#pragma unroll
            for (int mi = 0; mi < 2; mi++) {
                float4 v = *reinterpret_cast<const float4*>(
                    &As[(((wm * 2 + mi) * 16 + ks) << 7) + (lane << 2)]);
                af[mi][0] = __float_as_uint(v.x); af[mi][1] = __float_as_uint(v.y);
                af[mi][2] = __float_as_uint(v.z); af[mi][3] = __float_as_uint(v.w);
            }
            uint32_t bf[4][2];
#pragma unroll
            for (int ni = 0; ni < 4; ni++) {
                float2 v = *reinterpret_cast<const float2*>(
                    &Bs[(((wn * 4 + ni) * 16 + ks) << 6) + (lane << 1)]);
                bf[ni][0] = __float_as_uint(v.x); bf[ni][1] = __float_as_uint(v.y);
            }
#pragma unroll
            for (int mi = 0; mi < 2; mi++)
#pragma unroll
                for (int ni = 0; ni < 4; ni++)
                    mma_tf32(acc[mi][ni][0], acc[mi][ni][1], acc[mi][ni][2], acc[mi][ni][3],
                             af[mi][0], af[mi][1], af[mi][2], af[mi][3],
                             bf[ni][0], bf[ni][1]);
        }
    };

    auto epilogue = [&](int colbase) {
        float asr[2][2][2], adr[2][2][2];
#pragma unroll
        for (int mi = 0; mi < 2; mi++)
#pragma unroll
            for (int rh = 0; rh < 2; rh++)
#pragma unroll
                for (int hp = 0; hp < 2; hp++) { asr[mi][rh][hp] = 0.f; adr[mi][rh][hp] = 0.f; }
#pragma unroll
        for (int mi = 0; mi < 2; mi++) {
#pragma unroll
            for (int ni = 0; ni < 4; ni++) {
                int cb = colbase + wn * 32 + ni * 8 + (qd << 1);
                int r = row0 + wm * 32 + mi * 16 + grp;
                float v0 = acc[mi][ni][0], v1 = acc[mi][ni][1];
                float v2 = acc[mi][ni][2], v3 = acc[mi][ni][3];
                int hp = ni >> 1;
                float a0 = asv[cb], a1 = asv[cb + 1];
                float d0 = adv[cb], d1 = adv[cb + 1];
                asr[mi][0][hp] += v0 * a0 + v1 * a1;
                asr[mi][1][hp] += v2 * a0 + v3 * a1;
                adr[mi][0][hp] += v0 * d0 + v1 * d1;
                adr[mi][1][hp] += v2 * d0 + v3 * d1;
                if (r < NN)
                    *reinterpret_cast<float2*>(&g_hw[(size_t)r * 128 + cb]) = make_float2(v0, v1);
                if (r + 8 < NN)
                    *reinterpret_cast<float2*>(&g_hw[(size_t)(r + 8) * 128 + cb]) = make_float2(v2, v3);
            }
        }
#pragma unroll
        for (int mi = 0; mi < 2; mi++)
#pragma unroll
            for (int rh = 0; rh < 2; rh++)
#pragma unroll
                for (int hp = 0; hp < 2; hp++) {
                    float a = asr[mi][rh][hp], d = adr[mi][rh][hp];
                    a += __shfl_xor_sync(0xffffffffu, a, 1);
                    a += __shfl_xor_sync(0xffffffffu, a, 2);
                    d += __shfl_xor_sync(0xffffffffu, d, 1);
                    d += __shfl_xor_sync(0xffffffffu, d, 2);
                    asr[mi][rh][hp] = a; adr[mi][rh][hp] = d;
                }
        if (qd == 0) {
            int h0 = (colbase + wn * 32) >> 4;
#pragma unroll
            for (int mi = 0; mi < 2; mi++)
#pragma unroll
                for (int rh = 0; rh < 2; rh++) {
                    int r = row0 + wm * 32 + mi * 16 + grp + rh * 8;
                    if (r < NN) {
#pragma unroll
                        for (int hp = 0; hp < 2; hp++) {
                            g_as[r * 8 + h0 + hp] = asr[mi][rh][hp];
                            g_ad[r * 8 + h0 + hp] = adr[mi][rh][hp];
                        }
                    }
                }
        }
    };

#pragma unroll
    for (int mi = 0; mi < 2; mi++)
#pragma unroll
        for (int ni = 0; ni < 4; ni++)
#pragma unroll
            for (int j = 0; j < 4; j++) acc[mi][ni][j] = 0.f;
    compute(0, 8);
    __syncthreads();
#pragma unroll
    for (int j = 0; j < 8; j++) {
        int g = j * 256 + tid;
        int r = g >> 4, c = 64 + (g & 15) * 4;
#pragma unroll
        for (int e = 0; e < 4; e++)
            As[a_idx(r, c + e)] = __uint_as_float(f2tf32((&pf[j].x)[e]));
    }
    __syncthreads();
    compute(8, 16);
    float4 pfB[8];
#pragma unroll
    for (int j = 0; j < 8; j++) {
        int i = tid * 4 + j * 1024;
        int k = i >> 6, n = i & 63;
        pfB[j] = *reinterpret_cast<const float4*>(&W[(size_t)k * 128 + 64 + n]);
    }
    epilogue(0);

    __syncthreads();
#pragma unroll
    for (int j = 0; j < 8; j++) {
        int i = tid * 4 + j * 1024;
        int k = i >> 6, n = i & 63;
#pragma unroll
        for (int e = 0; e < 4; e++)
            Bs[b_idx(n + e, k)] = __uint_as_float(f2tf32((&pfB[j].x)[e]));
    }
    __syncthreads();
#pragma unroll
    for (int mi = 0; mi < 2; mi++)
#pragma unroll
        for (int ni = 0; ni < 4; ni++)
#pragma unroll
            for (int j = 0; j < 4; j++) acc[mi][ni][j] = 0.f;
    compute(0, 16);
    epilogue(64);
}

// ================= fused MLP head (R11-proven) ==============================
__global__ void __launch_bounds__(256, 2) mlp_kernel(
    const float* __restrict__ W1, const float* __restrict__ b1,
    const float* __restrict__ W2, const float* __restrict__ b2,
    const float* __restrict__ W3, const float* __restrict__ b3,
    float* __restrict__ out) {
    extern __shared__ float sm[];
    float* As = sm;
    float* Bs = sm + 16384;
    __shared__ float hsum[128];
    int tid = threadIdx.x;
    int row0 = blockIdx.x * 128;
    int w = tid >> 5, lane = tid & 31;
    int wm = w >> 1, wn = w & 1;
    int grp = lane >> 2, qd = lane & 3;

#pragma unroll
    for (int j = 0; j < 8; j++) {
        int i = tid * 4 + j * 1024;
        int k = i >> 6, n = i & 63;
        float4 wv = *reinterpret_cast<const float4*>(&W1[(size_t)k * 128 + n]);
#pragma unroll
        for (int e = 0; e < 4; e++)
            Bs[b_idx(n + e, k)] = __uint_as_float(f2tf32((&wv.x)[e]));
    }
    for (int g = tid; g < 2048; g += 256) {
        int r = g >> 4, c = (g & 15) * 4;
        int gr = row0 + r; if (gr >= NN) gr = NN - 1;
        float4 v = *reinterpret_cast<const float4*>(&g_h[(size_t)gr * 128 + c]);
#pragma unroll
        for (int e = 0; e < 4; e++)
            As[a_idx(r, c + e)] = __uint_as_float(f2tf32((&v.x)[e]));
    }
    float4 pf[8];
#pragma unroll
    for (int j = 0; j < 8; j++) {
        int g = j * 256 + tid;
        int r = g >> 4, c = 64 + (g & 15) * 4;
        int gr = row0 + r; if (gr >= NN) gr = NN - 1;
        pf[j] = *reinterpret_cast<const float4*>(&g_h[(size_t)gr * 128 + c]);
    }
    __syncthreads();

    float acc0[2][4][4], acc1[2][4][4];
    auto compute = [&](float (&acc)[2][4][4], int ks0, int ks1) {
        for (int ks = ks0; ks < ks1; ks++) {
            uint32_t af[2][4];
#pragma unroll
            for (int mi = 0; mi < 2; mi++) {
                float4 v = *reinterpret_cast<const float4*>(
                    &As[(((wm * 2 + mi) * 16 + ks) << 7) + (lane << 2)]);
                af[mi][0] = __float_as_uint(v.x); af[mi][1] = __float_as_uint(v.y);
                af[mi][2] = __float_as_uint(v.z); af[mi][3] = __float_as_uint(v.w);
            }
            uint32_t bf[4][2];
#pragma unroll
            for (int ni = 0; ni < 4; ni++) {
                float2 v = *reinterpret_cast<const float2*>(
                    &Bs[(((wn * 4 + ni) * 16 + ks) << 6) + (lane << 1)]);
                bf[ni][0] = __float_as_uint(v.x); bf[ni][1] = __float_as_uint(v.y);
            }
#pragma unroll
            for (int mi = 0; mi < 2; mi++)
#pragma unroll
                for (int ni = 0; ni < 4; ni++)
                    mma_tf32(acc[mi][ni][0], acc[mi][ni][1], acc[mi][ni][2], acc[mi][ni][3],
                             af[mi][0], af[mi][1], af[mi][2], af[mi][3],
                             bf[ni][0], bf[ni][1]);
        }
    };

#pragma unroll
    for (int mi = 0; mi < 2; mi++)
#pragma unroll
        for (int ni = 0; ni < 4; ni++)
#pragma unroll
            for (int j = 0; j < 4; j++) acc0[mi][ni][j] = 0.f;
    compute(acc0, 0, 8);
    __syncthreads();
#pragma unroll
    for (int j = 0; j < 8; j++) {
        int g = j * 256 + tid;
        int r = g >> 4, c = 64 + (g & 15) * 4;
#pragma unroll
        for (int e = 0; e < 4; e++)
            As[a_idx(r, c + e)] = __uint_as_float(f2tf32((&pf[j].x)[e]));
    }
    __syncthreads();
    compute(acc0, 8, 16);
    float4 pfB[8];
#pragma unroll
    for (int j = 0; j < 8; j++) {
        int i = tid * 4 + j * 1024;
        int k = i >> 6, n = i & 63;
        pfB[j] = *reinterpret_cast<const float4*>(&W1[(size_t)k * 128 + 64 + n]);
    }
    __syncthreads();
#pragma unroll
    for (int j = 0; j < 8; j++) {
        int i = tid * 4 + j * 1024;
        int k = i >> 6, n = i & 63;
#pragma unroll
        for (int e = 0; e < 4; e++)
            Bs[b_idx(n + e, k)] = __uint_as_float(f2tf32((&pfB[j].x)[e]));
    }
    __syncthreads();
#pragma unroll
    for (int mi = 0; mi < 2; mi++)
#pragma unroll
        for (int ni = 0; ni < 4; ni++)
#pragma unroll
            for (int j = 0; j < 4; j++) acc1[mi][ni][j] = 0.f;
    compute(acc1, 0, 16);
    __syncthreads();

#pragma unroll
    for (int mi = 0; mi < 2; mi++) {
#pragma unroll
        for (int ni = 0; ni < 4; ni++) {
            int c0 = wn * 32 + ni * 8 + (qd << 1);
            int r0 = wm * 32 + mi * 16 + grp;
            float bb0 = b1[c0], bb1 = b1[c0 + 1];
            As[a_idx(r0, c0)]     = __uint_as_float(f2tf32(fmaxf(acc0[mi][ni][0] + bb0, 0.f)));
            As[a_idx(r0, c0 + 1)] = __uint_as_float(f2tf32(fmaxf(acc0[mi][ni][1] + bb1, 0.f)));
            As[a_idx(r0 + 8, c0)]     = __uint_as_float(f2tf32(fmaxf(acc0[mi][ni][2] + bb0, 0.f)));
            As[a_idx(r0 + 8, c0 + 1)] = __uint_as_float(f2tf32(fmaxf(acc0[mi][ni][3] + bb1, 0.f)));
            int c1 = c0 + 64;
            float cb0 = b1[c1], cb1 = b1[c1 + 1];
            As[a_idx(r0, c1)]     = __uint_as_float(f2tf32(fmaxf(acc1[mi][ni][0] + cb0, 0.f)));
            As[a_idx(r0, c1 + 1)] = __uint_as_float(f2tf32(fmaxf(acc1[mi][ni][1] + cb1, 0.f)));
            As[a_idx(r0 + 8, c1)]     = __uint_as_float(f2tf32(fmaxf(acc1[mi][ni][2] + cb0, 0.f)));
            As[a_idx(r0 + 8, c1 + 1)] = __uint_as_float(f2tf32(fmaxf(acc1[mi][ni][3] + cb1, 0.f)));
        }
    }
#pragma unroll
    for (int j = 0; j < 8; j++) {
        int i = tid * 4 + j * 1024;
        int k = i >> 6, n = i & 63;
        float4 wv = *reinterpret_cast<const float4*>(&W2[(size_t)k * 64 + n]);
#pragma unroll
        for (int e = 0; e < 4; e++)
            Bs[b_idx(n + e, k)] = __uint_as_float(f2tf32((&wv.x)[e]));
    }
    __syncthreads();

#pragma unroll
    for (int mi = 0; mi < 2; mi++)
#pragma unroll
        for (int ni = 0; ni < 4; ni++)
#pragma unroll
            for (int j = 0; j < 4; j++) acc0[mi][ni][j] = 0.f;
    compute(acc0, 0, 16);

    float pr[2][2] = {{0.f, 0.f}, {0.f, 0.f}};
#pragma unroll
    for (int mi = 0; mi < 2; mi++) {
#pragma unroll
        for (int ni = 0; ni < 4; ni++) {
            int cb = wn * 32 + ni * 8 + (qd << 1);
            float bb0 = b2[cb], bb1 = b2[cb + 1];
            float w0 = W3[cb], w1 = W3[cb + 1];
            float v0 = fmaxf(acc0[mi][ni][0] + bb0, 0.f);
            float v1 = fmaxf(acc0[mi][ni][1] + bb1, 0.f);
            float v2 = fmaxf(acc0[mi][ni][2] + bb0, 0.f);
            float v3 = fmaxf(acc0[mi][ni][3] + bb1, 0.f);
            pr[mi][0] += v0 * w0 + v1 * w1;
            pr[mi][1] += v2 * w0 + v3 * w1;
        }
    }
#pragma unroll
    for (int mi = 0; mi < 2; mi++)
#pragma unroll
        for (int rh = 0; rh < 2; rh++) {
            float p = pr[mi][rh];
            p += __shfl_xor_sync(0xffffffffu, p, 1);
            p += __shfl_xor_sync(0xffffffffu, p, 2);
            pr[mi][rh] = p;
        }
    if (wn == 0 && qd == 0) {
#pragma unroll
        for (int mi = 0; mi < 2; mi++)
#pragma unroll
            for (int rh = 0; rh < 2; rh++)
                hsum[wm * 32 + mi * 16 + grp + rh * 8] = pr[mi][rh];
    }
    __syncthreads();
    if (wn == 1 && qd == 0) {
        float bb = b3[0];
#pragma unroll
        for (int mi = 0; mi < 2; mi++)
#pragma unroll
            for (int rh = 0; rh < 2; rh++) {
                int local = wm * 32 + mi * 16 + grp + rh * 8;
                int r = row0 + local;
                if (r < NN) out[r] = hsum[local] + pr[mi][rh] + bb;
            }
    }
}

// ---------------- CSR build (2 edges/thread; no memset) ----------------------
__global__ void count_kernel(const int* __restrict__ dst) {
    int e2 = blockIdx.x * blockDim.x + threadIdx.x;
    int e = e2 * 2;
    if (e < EE) {
        int2 d = *reinterpret_cast<const int2*>(&dst[e]);
        atomicAdd(&g_cnt[d.x], 1);
        atomicAdd(&g_cnt[d.y], 1);
    }
}
__global__ void scan1() {
    __shared__ int sm[512];
    int i = blockIdx.x * 512 + threadIdx.x;
    int v = (i < NN) ? g_cnt[i] : 0;
    sm[threadIdx.x] = v;
    __syncthreads();
    for (int off = 1; off < 512; off <<= 1) {
        int t = (threadIdx.x >= off) ? sm[threadIdx.x - off] : 0;
        __syncthreads();
        sm[threadIdx.x] += t;
        __syncthreads();
    }
    if (i < NN) g_incl[i] = sm[threadIdx.x];
    if (threadIdx.x == 511) g_bsum[blockIdx.x] = sm[511];
}
// merged scan2+scan3; also re-zeroes g_cnt for the next graph replay
__global__ void __launch_bounds__(256) scan23() {
    __shared__ int tmp[128];
    __shared__ int bex[SCANB];
    int tid = threadIdx.x;
    if (tid < 128) tmp[tid] = (tid < SCANB) ? g_bsum[tid] : 0;
    __syncthreads();
    int myv = (tid < 128) ? tmp[tid] : 0;
    for (int off = 1; off < 128; off <<= 1) {
        int t = (tid < 128 && tid >= off) ? tmp[tid - off] : 0;
        __syncthreads();
        if (tid < 128) tmp[tid] += t;
        __syncthreads();
    }
    if (tid < SCANB) bex[tid] = tmp[tid] - myv;
    __syncthreads();
    int i = blockIdx.x * blockDim.x + tid;
    if (i < NN) {
        int off = g_incl[i] - g_cnt[i] + bex[i >> 9];
        g_rowoff[i] = off;
        g_cursor[i] = off;
        g_cnt[i] = 0;   // reset for next run (graph replay correctness)
    }
    if (i == 0) g_rowoff[NN] = EE;
}
__global__ void scatter(const int* __restrict__ src, const int* __restrict__ dst) {
    int e2 = blockIdx.x * blockDim.x + threadIdx.x;
    int e = e2 * 2;
    if (e < EE) {
        int2 d = *reinterpret_cast<const int2*>(&dst[e]);
        int2 s = *reinterpret_cast<const int2*>(&src[e]);
        int p0 = atomicAdd(&g_cursor[d.x], 1);
        int p1 = atomicAdd(&g_cursor[d.y], 1);
        g_csr[p0] = s.x;
        g_csr[p1] = s.y;
    }
}

__device__ __forceinline__ float lrelu(float t) { return t > 0.f ? t : 0.2f * t; }

// ---------------- ONE-sweep aggregate, 4-way unroll (R13-proven) -------------
__global__ void __launch_bounds__(256) aggregate_kernel(
    const float* __restrict__ gb, const float* __restrict__ lng,
    const float* __restrict__ lnb) {
    int n = (blockIdx.x * blockDim.x + threadIdx.x) >> 5;
    if (n >= NN) return;
    int lane = threadIdx.x & 31;
    int beg = g_rowoff[n], end = g_rowoff[n + 1];
    int mh = lane >> 2;
    int c0 = lane * 4;

    float admh = g_ad[n * 8 + mh];
    float asmh = g_as[n * 8 + mh];
    float wself = __expf(lrelu(asmh + admh));
    float den = wself;
    float a0, a1, a2, a3;
    {
        float4 v = *reinterpret_cast<const float4*>(&g_hw[(size_t)n * 128 + c0]);
        a0 = v.x * wself; a1 = v.y * wself; a2 = v.z * wself; a3 = v.w * wself;
    }
    int i = beg;
    for (; i + 4 <= end; i += 4) {
        int s0 = g_csr[i], s1 = g_csr[i + 1], s2 = g_csr[i + 2], s3 = g_csr[i + 3];
        float l0 = g_as[s0 * 8 + mh], l1 = g_as[s1 * 8 + mh];
        float l2 = g_as[s2 * 8 + mh], l3 = g_as[s3 * 8 + mh];
        float4 v0 = *reinterpret_cast<const float4*>(&g_hw[(size_t)s0 * 128 + c0]);
        float4 v1 = *reinterpret_cast<const float4*>(&g_hw[(size_t)s1 * 128 + c0]);
        float4 v2 = *reinterpret_cast<const float4*>(&g_hw[(size_t)s2 * 128 + c0]);
        float4 v3 = *reinterpret_cast<const float4*>(&g_hw[(size_t)s3 * 128 + c0]);
        float w0 = __expf(lrelu(l0 + admh));
        float w1 = __expf(lrelu(l1 + admh));
        float w2 = __expf(lrelu(l2 + admh));
        float w3 = __expf(lrelu(l3 + admh));
        den += (w0 + w1) + (w2 + w3);
        a0 = fmaf(v0.x, w0, fmaf(v1.x, w1, fmaf(v2.x, w2, fmaf(v3.x, w3, a0))));
        a1 = fmaf(v0.y, w0, fmaf(v1.y, w1, fmaf(v2.y, w2, fmaf(v3.y, w3, a1))));
        a2 = fmaf(v0.z, w0, fmaf(v1.z, w1, fmaf(v2.z, w2, fmaf(v3.z, w3, a2))));
        a3 = fmaf(v0.w, w0, fmaf(v1.w, w1, fmaf(v2.w, w2, fmaf(v3.w, w3, a3))));
    }
    for (; i < end; i++) {
        int s = g_csr[i];
        float wgt = __expf(lrelu(g_as[s * 8 + mh] + admh));
        float4 v = *reinterpret_cast<const float4*>(&g_hw[(size_t)s * 128 + c0]);
        den += wgt;
        a0 = fmaf(v.x, wgt, a0);
        a1 = fmaf(v.y, wgt, a1);
        a2 = fmaf(v.z, wgt, a2);
        a3 = fmaf(v.w, wgt, a3);
    }
    float iv = 1.0f / den;
    float4 b4 = *reinterpret_cast<const float4*>(&gb[c0]);
    float v0 = fmaxf(fmaf(a0, iv, b4.x), 0.f), v1 = fmaxf(fmaf(a1, iv, b4.y), 0.f);
    float v2 = fmaxf(fmaf(a2, iv, b4.z), 0.f), v3 = fmaxf(fmaf(a3, iv, b4.w), 0.f);
    float4 r4 = *reinterpret_cast<const float4*>(&g_h[(size_t)n * 128 + c0]);
    v0 += r4.x; v1 += r4.y; v2 += r4.z; v3 += r4.w;
    float s1 = v0 + v1 + v2 + v3;
    float s2 = v0 * v0 + v1 * v1 + v2 * v2 + v3 * v3;
#pragma unroll
    for (int off = 16; off; off >>= 1) {
        s1 += __shfl_xor_sync(0xffffffffu, s1, off);
        s2 += __shfl_xor_sync(0xffffffffu, s2, off);
    }
    float mu = s1 * (1.f / 128.f);
    float var = s2 * (1.f / 128.f) - mu * mu;
    float rstd = rsqrtf(fmaxf(var, 0.f) + 1e-5f);
    float4 g4 = *reinterpret_cast<const float4*>(&lng[c0]);
    float4 bb4 = *reinterpret_cast<const float4*>(&lnb[c0]);
    float4 o;
    o.x = (v0 - mu) * rstd * g4.x + bb4.x;
    o.y = (v1 - mu) * rstd * g4.y + bb4.y;
    o.z = (v2 - mu) * rstd * g4.z + bb4.z;
    o.w = (v3 - mu) * rstd * g4.w + bb4.w;
    *reinterpret_cast<float4*>(&g_h[(size_t)n * 128 + c0]) = o;
}

// ---------------- launch ----------------------------------------------------
extern "C" void kernel_launch(void* const* d_in, const int* in_sizes, int n_in,
                              void* d_out, int out_size) {
    const float* x = (const float*)d_in[0];
    const int* ei = (const int*)d_in[1];
    const int* src = ei;
    const int* dst = ei + EE;
    const float* W_in = (const float*)d_in[3];
    const float* b_in = (const float*)d_in[4];
    float* out = (float*)d_out;

    float* p_h = nullptr;
    cudaGetSymbolAddress((void**)&p_h, g_h);

    const int SMEM_GEMM = (16384 + 8192) * 4;  // 96 KB
    cudaFuncSetAttribute(gat_gemm<true>,  cudaFuncAttributeMaxDynamicSharedMemorySize, SMEM_GEMM);
    cudaFuncSetAttribute(gat_gemm<false>, cudaFuncAttributeMaxDynamicSharedMemorySize, SMEM_GEMM);
    cudaFuncSetAttribute(mlp_kernel,      cudaFuncAttributeMaxDynamicSharedMemorySize, SMEM_GEMM);
    const int NCTA = (NN + 127) / 128;  // 391
    const int E2 = EE / 2;              // 300000

    // fork the CSR build onto a second stream, overlapping the layer-0 GEMM
    cudaStream_t s2;
    cudaEvent_t ev1, ev2;
    cudaStreamCreateWithFlags(&s2, cudaStreamNonBlocking);
    cudaEventCreateWithFlags(&ev1, cudaEventDisableTiming);
    cudaEventCreateWithFlags(&ev2, cudaEventDisableTiming);

    cudaEventRecord(ev1, 0);
    cudaStreamWaitEvent(s2, ev1, 0);
    count_kernel<<<(E2 + 255) / 256, 256, 0, s2>>>(dst);
    scan1<<<(NN + 511) / 512, 512, 0, s2>>>();
    scan23<<<(NN + 255) / 256, 256, 0, s2>>>();
    scatter<<<(E2 + 255) / 256, 256, 0, s2>>>(src, dst);
    cudaEventRecord(ev2, s2);

    // layer 0 GEMM on main stream (independent of CSR)
    gat_gemm<true><<<NCTA, 256, SMEM_GEMM>>>(
        nullptr, x, W_in, b_in, (const float*)d_in[5],
        (const float*)d_in[6], (const float*)d_in[7]);
    cudaStreamWaitEvent(0, ev2, 0);   // join: aggregate needs the CSR

    for (int l = 0; l < 3; l++) {
        const float* gb = (const float*)d_in[8 + 6 * l];
        const float* lg = (const float*)d_in[9 + 6 * l];
        const float* lb = (const float*)d_in[10 + 6 * l];
        if (l > 0) {
            const float* W  = (const float*)d_in[5 + 6 * l];
            const float* as = (const float*)d_in[6 + 6 * l];
            const float* ad = (const float*)d_in[7 + 6 * l];
            gat_gemm<false><<<NCTA, 256, SMEM_GEMM>>>(p_h, nullptr, nullptr, nullptr, W, as, ad);
        }
        aggregate_kernel<<<(NN + 7) / 8, 256>>>(gb, lg, lb);
    }
    mlp_kernel<<<NCTA, 256, SMEM_GEMM>>>((const float*)d_in[23], (const float*)d_in[24],
                                         (const float*)d_in[25], (const float*)d_in[26],
                                         (const float*)d_in[27], (const float*)d_in[28], out);
}